// round 3
// baseline (speedup 1.0000x reference)
#include <cuda_runtime.h>
#include <cstdint>
#include <cstddef>

// Problem shape (fixed for this registry entry)
#define B_ROWS 4096
#define T_LEN  8192
#define K_WIN  5

// Pass-1 tiling
#define ROWS   32                 // rows per block (one consumer lane per row)
#define WTILE  64                 // timesteps per tile
#define NSTAGE 3                  // ring stages
#define NTILES (T_LEN / WTILE)    // 128
#define CHUNKS (WTILE / 4 + 1)    // 17 float4 per row (16 data + 1 pad -> conflict-free LDS.128)

#define X_F4   (NSTAGE * 3 * ROWS * CHUNKS)   // x tiles, float4 units
#define SAL_F4 (NSTAGE * ROWS * CHUNKS)       // sal tiles, float4 units
#define SMEM_BYTES ((X_F4 + SAL_F4) * 16 + 2 * NSTAGE * 8)

__device__ float g_inv[B_ROWS];   // per-row 1/(max+eps) scratch (static device global: allowed)

// ---------------- mbarrier helpers ----------------
__device__ __forceinline__ void mbar_init(unsigned addr, unsigned count) {
    asm volatile("mbarrier.init.shared.b64 [%0], %1;" :: "r"(addr), "r"(count) : "memory");
}
__device__ __forceinline__ void mbar_arrive(unsigned addr) {
    asm volatile("mbarrier.arrive.shared.b64 _, [%0];" :: "r"(addr) : "memory");
}
__device__ __forceinline__ void mbar_wait(unsigned addr, unsigned parity) {
    unsigned done;
    asm volatile("{\n\t.reg .pred p;\n\t"
                 "mbarrier.try_wait.parity.acquire.cta.shared::cta.b64 p, [%1], %2;\n\t"
                 "selp.b32 %0, 1, 0, p;\n\t}"
                 : "=r"(done) : "r"(addr), "r"(parity) : "memory");
    if (!done) {
        asm volatile("{\n\t.reg .pred P1;\n\t"
                     "WL_%=:\n\t"
                     "mbarrier.try_wait.parity.acquire.cta.shared::cta.b64 P1, [%0], %1, 0x989680;\n\t"
                     "@P1 bra.uni WD_%=;\n\t"
                     "bra.uni WL_%=;\n\t"
                     "WD_%=:\n\t}"
                     :: "r"(addr), "r"(parity) : "memory");
    }
}
__device__ __forceinline__ void cp_async16(unsigned smem_addr, const void* gptr) {
    asm volatile("cp.async.cg.shared.global [%0], [%1], 16;" :: "r"(smem_addr), "l"(gptr));
}
__device__ __forceinline__ void cp_async_arrive_noinc(unsigned mbar_addr) {
    asm volatile("cp.async.mbarrier.arrive.noinc.shared.b64 [%0];" :: "r"(mbar_addr) : "memory");
}

// ---------------- top-5 streaming insert (matches lax.top_k tie-break: strictly-greater) ----
__device__ __forceinline__ void top5_insert(float s, int t, float tv[5], int ti[5]) {
    if (s > tv[4]) {
        if (s > tv[0]) {
            tv[4]=tv[3]; ti[4]=ti[3]; tv[3]=tv[2]; ti[3]=ti[2];
            tv[2]=tv[1]; ti[2]=ti[1]; tv[1]=tv[0]; ti[1]=ti[0];
            tv[0]=s; ti[0]=t;
        } else if (s > tv[1]) {
            tv[4]=tv[3]; ti[4]=ti[3]; tv[3]=tv[2]; ti[3]=ti[2];
            tv[2]=tv[1]; ti[2]=ti[1]; tv[1]=s; ti[1]=t;
        } else if (s > tv[2]) {
            tv[4]=tv[3]; ti[4]=ti[3]; tv[3]=tv[2]; ti[3]=ti[2];
            tv[2]=s; ti[2]=t;
        } else if (s > tv[3]) {
            tv[4]=tv[3]; ti[4]=ti[3]; tv[3]=s; ti[3]=t;
        } else {
            tv[4]=s; ti[4]=t;
        }
    }
}

__device__ __forceinline__ float lif_step(float xa, float xp, float xb,
                                          float d0, float d1, float d2,
                                          float w0, float w1, float w2,
                                          float& v0, float& v1, float& v2) {
    v0 = fmaf(d0, v0, xa);
    v1 = fmaf(d1, v1, xp);
    v2 = fmaf(d2, v2, xb);
    float sal = 0.0f;
    if (v0 >= 1.0f) { v0 -= 1.0f; sal += w0; }
    if (v1 >= 1.0f) { v1 -= 1.0f; sal += w1; }
    if (v2 >= 1.0f) { v2 -= 1.0f; sal += w2; }
    return sal;
}

// =====================================================================================
// Pass 1: warp-specialized LIF scan.
//   warp 0 (producer): cp.async x-tiles into 3-stage ring; coalesced STG of sal tiles.
//   warp 1 (consumer): one lane per row; 3-channel LIF; raw sal -> smem; top-5 + max.
// =====================================================================================
extern "C" __global__ void __launch_bounds__(64, 1)
msa_pass1(const float* __restrict__ amp, const float* __restrict__ pitch,
          const float* __restrict__ bnd, const float* __restrict__ decay,
          const float* __restrict__ weights, float* __restrict__ out)
{
    extern __shared__ float4 smem[];
    float4* xs = smem;              // [stage][3][ROWS][CHUNKS]
    float4* ss = smem + X_F4;       // [stage][ROWS][CHUNKS]
    unsigned mbar_base = (unsigned)__cvta_generic_to_shared(smem + X_F4 + SAL_F4);
    // full[s] at mbar_base + s*8 ; empty[s] at mbar_base + (NSTAGE+s)*8

    const int tid  = threadIdx.x;
    const int lane = tid & 31;
    const int warp = tid >> 5;
    const int b0   = blockIdx.x * ROWS;

    if (tid == 0) {
        #pragma unroll
        for (int s = 0; s < NSTAGE; ++s) {
            mbar_init(mbar_base + s * 8, 32);              // full: 32 producer arrivals
            mbar_init(mbar_base + (NSTAGE + s) * 8, 32);   // empty: 32 consumer arrivals
        }
        asm volatile("fence.proxy.async.shared::cta;" ::: "memory");
    }
    __syncthreads();

    float* out_sal = out + B_ROWS;                       // sal region
    float* out_idx = out + B_ROWS + (size_t)B_ROWS * T_LEN;  // topk_idx region (as float)

    if (warp == 0) {
        // ---------------- producer ----------------
        const float* chp0 = amp;
        const float* chp1 = pitch;
        const float* chp2 = bnd;
        const int rr = lane >> 4;     // 0/1 : row within pair
        const int cc = lane & 15;     // chunk (16B) within row

        for (int i = 0; i < NTILES + NSTAGE; ++i) {
            const int s = i % NSTAGE;
            if (i >= NSTAGE) {
                // consumer finished tile i-NSTAGE in slot s -> drain its sal, slot reusable
                mbar_wait(mbar_base + (NSTAGE + s) * 8, (unsigned)(((i - NSTAGE) / NSTAGE) & 1));
                const int j = i - NSTAGE;
                const size_t t0 = (size_t)j * WTILE;
                const float4* salst = ss + (size_t)s * ROWS * CHUNKS;
                #pragma unroll
                for (int q = 0; q < 16; ++q) {
                    const int r = q * 2 + rr;
                    float4 v = salst[r * CHUNKS + cc];
                    *reinterpret_cast<float4*>(out_sal + (size_t)(b0 + r) * T_LEN + t0 + cc * 4) = v;
                }
            }
            if (i < NTILES) {
                const size_t t0 = (size_t)i * WTILE;
                #pragma unroll
                for (int c = 0; c < 3; ++c) {
                    const float* src = (c == 0) ? chp0 : (c == 1) ? chp1 : chp2;
                    float4* dst = xs + ((size_t)(s * 3 + c)) * ROWS * CHUNKS;
                    #pragma unroll
                    for (int q = 0; q < 16; ++q) {
                        const int r = q * 2 + rr;
                        const float* g = src + (size_t)(b0 + r) * T_LEN + t0 + cc * 4;
                        unsigned sa = (unsigned)__cvta_generic_to_shared(dst + r * CHUNKS + cc);
                        cp_async16(sa, g);
                    }
                }
                cp_async_arrive_noinc(mbar_base + s * 8);
            }
        }
    } else {
        // ---------------- consumer: one lane per row ----------------
        const int r = lane;
        const float d0 = decay[0],   d1 = decay[1],   d2 = decay[2];
        const float w0 = weights[0], w1 = weights[1], w2 = weights[2];

        float v0 = 0.0f, v1 = 0.0f, v2 = 0.0f;
        float tv[5] = {-1.0f, -1.0f, -1.0f, -1.0f, -1.0f};
        int   ti[5] = {0, 0, 0, 0, 0};

        for (int i = 0; i < NTILES; ++i) {
            const int s = i % NSTAGE;
            mbar_wait(mbar_base + s * 8, (unsigned)((i / NSTAGE) & 1));

            const float4* A  = xs + ((size_t)(s * 3 + 0) * ROWS + r) * CHUNKS;
            const float4* P  = xs + ((size_t)(s * 3 + 1) * ROWS + r) * CHUNKS;
            const float4* Bq = xs + ((size_t)(s * 3 + 2) * ROWS + r) * CHUNKS;
            float4* SO = ss + ((size_t)s * ROWS + r) * CHUNKS;
            const int tbase = i * WTILE;

            #pragma unroll
            for (int g = 0; g < 16; ++g) {
                const float4 a = A[g];
                const float4 p = P[g];
                const float4 q = Bq[g];
                float4 so;
                so.x = lif_step(a.x, p.x, q.x, d0, d1, d2, w0, w1, w2, v0, v1, v2);
                top5_insert(so.x, tbase + 4 * g + 0, tv, ti);
                so.y = lif_step(a.y, p.y, q.y, d0, d1, d2, w0, w1, w2, v0, v1, v2);
                top5_insert(so.y, tbase + 4 * g + 1, tv, ti);
                so.z = lif_step(a.z, p.z, q.z, d0, d1, d2, w0, w1, w2, v0, v1, v2);
                top5_insert(so.z, tbase + 4 * g + 2, tv, ti);
                so.w = lif_step(a.w, p.w, q.w, d0, d1, d2, w0, w1, w2, v0, v1, v2);
                top5_insert(so.w, tbase + 4 * g + 3, tv, ti);
                SO[g] = so;
            }
            mbar_arrive(mbar_base + (NSTAGE + s) * 8);
        }

        // ---- row tail: normalization factor, mu, top-k indices ----
        const int b = b0 + r;
        const float denom = tv[0] + 1e-6f;        // tv[0] == row max of sal
        const float inv = 1.0f / denom;
        g_inv[b] = inv;

        const float n0 = tv[0] / denom, n1 = tv[1] / denom, n2 = tv[2] / denom,
                    n3 = tv[3] / denom, n4 = tv[4] / denom;
        const float avg = (n0 + n1 + n2 + n3 + n4) / 5.0f;
        const float mu  = 0.5f + 2.0f * tanhf(1.8f * avg);
        out[b] = mu;

        #pragma unroll
        for (int j = 0; j < K_WIN; ++j)
            out_idx[(size_t)b * K_WIN + j] = (float)ti[j];
    }
}

// =====================================================================================
// Pass 2: in-place row normalization of sal (sal *= 1/(rowmax+eps)), pure streaming.
// =====================================================================================
extern "C" __global__ void __launch_bounds__(256)
msa_pass2(float4* __restrict__ sal4)
{
    const int i = blockIdx.x * blockDim.x + threadIdx.x;   // one float4 per thread
    const int row = i / (T_LEN / 4);
    const float inv = __ldg(&g_inv[row]);
    float4 v = sal4[i];
    v.x *= inv; v.y *= inv; v.z *= inv; v.w *= inv;
    sal4[i] = v;
}

extern "C" void kernel_launch(void* const* d_in, const int* in_sizes, int n_in,
                              void* d_out, int out_size) {
    (void)in_sizes; (void)n_in; (void)out_size;
    const float* amp     = (const float*)d_in[0];
    const float* pitch   = (const float*)d_in[1];
    const float* bnd     = (const float*)d_in[2];
    const float* decay   = (const float*)d_in[3];
    const float* weights = (const float*)d_in[4];
    float* out = (float*)d_out;

    cudaFuncSetAttribute(msa_pass1, cudaFuncAttributeMaxDynamicSharedMemorySize, SMEM_BYTES);
    msa_pass1<<<B_ROWS / ROWS, 64, SMEM_BYTES>>>(amp, pitch, bnd, decay, weights, out);

    const int n4 = (B_ROWS * (T_LEN / 4));
    msa_pass2<<<n4 / 256, 256>>>(reinterpret_cast<float4*>(out + B_ROWS));
}

// round 4
// speedup vs baseline: 2.8294x; 2.8294x over previous
#include <cuda_runtime.h>
#include <cstdint>
#include <cstddef>

// Problem shape (fixed for this registry entry)
#define B_ROWS 4096
#define T_LEN  8192
#define K_WIN  5

// Pass-1 tiling
#define ROWS   32                 // rows per block (one consumer lane per row)
#define WTILE  128                // timesteps per tile
#define NSTAGE 3                  // ring stages
#define NTILES (T_LEN / WTILE)    // 64
#define CHUNKS (WTILE / 4 + 1)    // 33 float4 per row (32 data + 1 pad -> conflict-free LDS.128)
#define NG     (WTILE / 4)        // 32 float4 groups per row-tile

#define X_F4   (NSTAGE * 3 * ROWS * CHUNKS)   // x tiles, float4 units
#define SAL_F4 (NSTAGE * ROWS * CHUNKS)       // sal tiles, float4 units
#define SMEM_BYTES ((X_F4 + SAL_F4) * 16 + 2 * NSTAGE * 8)

__device__ float g_max[B_ROWS];   // per-row raw-sal max (pass1 -> pass2)

// ---------------- mbarrier helpers ----------------
__device__ __forceinline__ void mbar_init(unsigned addr, unsigned count) {
    asm volatile("mbarrier.init.shared.b64 [%0], %1;" :: "r"(addr), "r"(count) : "memory");
}
__device__ __forceinline__ void mbar_arrive(unsigned addr) {
    asm volatile("mbarrier.arrive.shared.b64 _, [%0];" :: "r"(addr) : "memory");
}
__device__ __forceinline__ void mbar_wait(unsigned addr, unsigned parity) {
    unsigned done;
    asm volatile("{\n\t.reg .pred p;\n\t"
                 "mbarrier.try_wait.parity.acquire.cta.shared::cta.b64 p, [%1], %2;\n\t"
                 "selp.b32 %0, 1, 0, p;\n\t}"
                 : "=r"(done) : "r"(addr), "r"(parity) : "memory");
    if (!done) {
        asm volatile("{\n\t.reg .pred P1;\n\t"
                     "WL_%=:\n\t"
                     "mbarrier.try_wait.parity.acquire.cta.shared::cta.b64 P1, [%0], %1, 0x989680;\n\t"
                     "@P1 bra.uni WD_%=;\n\t"
                     "bra.uni WL_%=;\n\t"
                     "WD_%=:\n\t}"
                     :: "r"(addr), "r"(parity) : "memory");
    }
}
__device__ __forceinline__ void cp_async16(unsigned smem_addr, const void* gptr) {
    asm volatile("cp.async.cg.shared.global [%0], [%1], 16;" :: "r"(smem_addr), "l"(gptr));
}
__device__ __forceinline__ void cp_async_arrive_noinc(unsigned mbar_addr) {
    asm volatile("cp.async.mbarrier.arrive.noinc.shared.b64 [%0];" :: "r"(mbar_addr) : "memory");
}

// ---------------- branchless 3-channel LIF step ----------------
// Recurrence numerics are bitwise identical to the reference path verified in R2:
//   a = fmaf(d, v, x);  if (a >= 1) v = a - 1 else v = a   (a-1 exact: a < 1.7)
// but compiled as FSETP (pred-as-data) + FSEL: 12-cycle chain, no @P guard, no branch.
__device__ __forceinline__ float lif_step(float xa, float xp, float xb,
                                          float d0, float d1, float d2,
                                          float w0, float w1, float w2,
                                          float& v0, float& v1, float& v2) {
    float a0 = fmaf(d0, v0, xa);
    float a1 = fmaf(d1, v1, xp);
    float a2 = fmaf(d2, v2, xb);
    float u0 = a0 - 1.0f;
    float u1 = a1 - 1.0f;
    float u2 = a2 - 1.0f;
    bool  p0 = (a0 >= 1.0f);
    bool  p1 = (a1 >= 1.0f);
    bool  p2 = (a2 >= 1.0f);
    v0 = p0 ? u0 : a0;
    v1 = p1 ? u1 : a1;
    v2 = p2 ? u2 : a2;
    float s0 = p0 ? w0 : 0.0f;
    float s1 = p1 ? w1 : 0.0f;
    float s2 = p2 ? w2 : 0.0f;
    return (s0 + s1) + s2;
}

// =====================================================================================
// Pass 1: warp-specialized LIF scan.
//   warp 0 (producer): cp.async x-tiles into 3-stage ring; coalesced STG of sal tiles.
//   warp 1 (consumer): one lane per row; branchless 3-channel LIF; raw sal -> smem;
//                      running row max only (top-k deferred to pass 2).
// =====================================================================================
extern "C" __global__ void __launch_bounds__(64, 1)
msa_pass1(const float* __restrict__ amp, const float* __restrict__ pitch,
          const float* __restrict__ bnd, const float* __restrict__ decay,
          const float* __restrict__ weights, float* __restrict__ out)
{
    extern __shared__ float4 smem[];
    float4* xs = smem;              // [stage][3][ROWS][CHUNKS]
    float4* ss = smem + X_F4;       // [stage][ROWS][CHUNKS]
    unsigned mbar_base = (unsigned)__cvta_generic_to_shared(smem + X_F4 + SAL_F4);
    // full[s] at mbar_base + s*8 ; empty[s] at mbar_base + (NSTAGE+s)*8

    const int tid  = threadIdx.x;
    const int lane = tid & 31;
    const int warp = tid >> 5;
    const int b0   = blockIdx.x * ROWS;

    if (tid == 0) {
        #pragma unroll
        for (int s = 0; s < NSTAGE; ++s) {
            mbar_init(mbar_base + s * 8, 32);              // full: 32 producer arrivals
            mbar_init(mbar_base + (NSTAGE + s) * 8, 32);   // empty: 32 consumer arrivals
        }
        asm volatile("fence.proxy.async.shared::cta;" ::: "memory");
    }
    __syncthreads();

    float* out_sal = out + B_ROWS;   // sal region

    if (warp == 0) {
        // ---------------- producer: lane = 16B chunk index (0..31) ----------------
        const int cc = lane;

        for (int i = 0; i < NTILES + NSTAGE; ++i) {
            const int s = i % NSTAGE;
            if (i >= NSTAGE) {
                // consumer finished tile i-NSTAGE in slot s -> drain its sal, slot reusable
                mbar_wait(mbar_base + (NSTAGE + s) * 8, (unsigned)(((i - NSTAGE) / NSTAGE) & 1));
                const int j = i - NSTAGE;
                const size_t t0 = (size_t)j * WTILE;
                const float4* salst = ss + (size_t)s * ROWS * CHUNKS;
                #pragma unroll
                for (int r = 0; r < ROWS; ++r) {
                    float4 v = salst[r * CHUNKS + cc];
                    *reinterpret_cast<float4*>(out_sal + (size_t)(b0 + r) * T_LEN + t0 + cc * 4) = v;
                }
            }
            if (i < NTILES) {
                const size_t t0 = (size_t)i * WTILE;
                #pragma unroll
                for (int c = 0; c < 3; ++c) {
                    const float* src = (c == 0) ? amp : (c == 1) ? pitch : bnd;
                    float4* dst = xs + ((size_t)(s * 3 + c)) * ROWS * CHUNKS;
                    #pragma unroll
                    for (int r = 0; r < ROWS; ++r) {
                        const float* g = src + (size_t)(b0 + r) * T_LEN + t0 + cc * 4;
                        unsigned sa = (unsigned)__cvta_generic_to_shared(dst + r * CHUNKS + cc);
                        cp_async16(sa, g);
                    }
                }
                cp_async_arrive_noinc(mbar_base + s * 8);
            }
        }
    } else {
        // ---------------- consumer: one lane per row ----------------
        const int r = lane;
        const float d0 = __ldg(&decay[0]),   d1 = __ldg(&decay[1]),   d2 = __ldg(&decay[2]);
        const float w0 = __ldg(&weights[0]), w1 = __ldg(&weights[1]), w2 = __ldg(&weights[2]);

        float v0 = 0.0f, v1 = 0.0f, v2 = 0.0f;
        float m = 0.0f;

        for (int i = 0; i < NTILES; ++i) {
            const int s = i % NSTAGE;
            mbar_wait(mbar_base + s * 8, (unsigned)((i / NSTAGE) & 1));

            const float4* A  = xs + ((size_t)(s * 3 + 0) * ROWS + r) * CHUNKS;
            const float4* P  = xs + ((size_t)(s * 3 + 1) * ROWS + r) * CHUNKS;
            const float4* Bq = xs + ((size_t)(s * 3 + 2) * ROWS + r) * CHUNKS;
            float4* SO = ss + ((size_t)s * ROWS + r) * CHUNKS;

            #pragma unroll
            for (int g = 0; g < NG; ++g) {
                const float4 a = A[g];
                const float4 p = P[g];
                const float4 q = Bq[g];
                float4 so;
                so.x = lif_step(a.x, p.x, q.x, d0, d1, d2, w0, w1, w2, v0, v1, v2);
                so.y = lif_step(a.y, p.y, q.y, d0, d1, d2, w0, w1, w2, v0, v1, v2);
                so.z = lif_step(a.z, p.z, q.z, d0, d1, d2, w0, w1, w2, v0, v1, v2);
                so.w = lif_step(a.w, p.w, q.w, d0, d1, d2, w0, w1, w2, v0, v1, v2);
                SO[g] = so;
                m = fmaxf(m, fmaxf(fmaxf(so.x, so.y), fmaxf(so.z, so.w)));
            }
            mbar_arrive(mbar_base + (NSTAGE + s) * 8);
        }

        g_max[b0 + r] = m;
    }
}

// ---------------- top-5 streaming insert (matches lax.top_k tie-break: strictly-greater) ----
__device__ __forceinline__ void top5_insert(float s, int t, float tv[5], int ti[5]) {
    if (s > tv[4]) {
        if (s > tv[0]) {
            tv[4]=tv[3]; ti[4]=ti[3]; tv[3]=tv[2]; ti[3]=ti[2];
            tv[2]=tv[1]; ti[2]=ti[1]; tv[1]=tv[0]; ti[1]=ti[0];
            tv[0]=s; ti[0]=t;
        } else if (s > tv[1]) {
            tv[4]=tv[3]; ti[4]=ti[3]; tv[3]=tv[2]; ti[3]=ti[2];
            tv[2]=tv[1]; ti[2]=ti[1]; tv[1]=s; ti[1]=t;
        } else if (s > tv[2]) {
            tv[4]=tv[3]; ti[4]=ti[3]; tv[3]=tv[2]; ti[3]=ti[2];
            tv[2]=s; ti[2]=t;
        } else if (s > tv[3]) {
            tv[4]=tv[3]; ti[4]=ti[3]; tv[3]=s; ti[3]=t;
        } else {
            tv[4]=s; ti[4]=t;
        }
    }
}

// =====================================================================================
// Pass 2: one warp per row. Streams the row once: normalizes sal in place (×inv),
// tracks per-lane top-5 of normalized values, warp-merges with exact lax.top_k
// tie-breaking (value desc, index asc), computes mu, writes mu + topk_idx.
// =====================================================================================
#define P2_WARPS 8
extern "C" __global__ void __launch_bounds__(P2_WARPS * 32)
msa_pass2(float* __restrict__ out)
{
    const int warp = threadIdx.x >> 5;
    const int lane = threadIdx.x & 31;
    const int row  = blockIdx.x * P2_WARPS + warp;

    const float inv = 1.0f / (g_max[row] + 1e-6f);
    float4* sal4 = reinterpret_cast<float4*>(out + B_ROWS) + (size_t)row * (T_LEN / 4);

    float tv[5] = {-1.0f, -1.0f, -1.0f, -1.0f, -1.0f};
    int   ti[5] = {0, 0, 0, 0, 0};

    #pragma unroll 4
    for (int it = 0; it < T_LEN / 4 / 32; ++it) {        // 64 iterations
        const int c = it * 32 + lane;
        float4 v = sal4[c];
        v.x *= inv; v.y *= inv; v.z *= inv; v.w *= inv;
        const int t = c * 4;
        top5_insert(v.x, t + 0, tv, ti);
        top5_insert(v.y, t + 1, tv, ti);
        top5_insert(v.z, t + 2, tv, ti);
        top5_insert(v.w, t + 3, tv, ti);
        sal4[c] = v;
    }

    // ---- warp merge: 5 rounds of 64-bit argmax (valbits<<32 | ~idx) ----
    float rv[5]; int ri[5];
    #pragma unroll
    for (int k = 0; k < K_WIN; ++k) {
        unsigned long long key = (tv[0] >= 0.0f)
            ? ((((unsigned long long)__float_as_uint(tv[0])) << 32) | (unsigned)(~(unsigned)ti[0]))
            : 0ULL;
        unsigned long long red = key;
        #pragma unroll
        for (int off = 16; off > 0; off >>= 1) {
            unsigned long long o = __shfl_xor_sync(0xffffffffu, red, off);
            red = (o > red) ? o : red;
        }
        if (key == red && red != 0ULL) {   // this lane's head won: pop (shift down)
            tv[0]=tv[1]; ti[0]=ti[1];
            tv[1]=tv[2]; ti[1]=ti[2];
            tv[2]=tv[3]; ti[2]=ti[3];
            tv[3]=tv[4]; ti[3]=ti[4];
            tv[4]=-1.0f;
        }
        rv[k] = __uint_as_float((unsigned)(red >> 32));
        ri[k] = (int)(~(unsigned)(red & 0xFFFFFFFFu));
    }

    if (lane == 0) {
        const float avg = (rv[0] + rv[1] + rv[2] + rv[3] + rv[4]) * 0.2f;
        out[row] = 0.5f + 2.0f * tanhf(1.8f * avg);
        float* out_idx = out + B_ROWS + (size_t)B_ROWS * T_LEN;
        #pragma unroll
        for (int k = 0; k < K_WIN; ++k)
            out_idx[(size_t)row * K_WIN + k] = (float)ri[k];
    }
}

extern "C" void kernel_launch(void* const* d_in, const int* in_sizes, int n_in,
                              void* d_out, int out_size) {
    (void)in_sizes; (void)n_in; (void)out_size;
    const float* amp     = (const float*)d_in[0];
    const float* pitch   = (const float*)d_in[1];
    const float* bnd     = (const float*)d_in[2];
    const float* decay   = (const float*)d_in[3];
    const float* weights = (const float*)d_in[4];
    float* out = (float*)d_out;

    cudaFuncSetAttribute(msa_pass1, cudaFuncAttributeMaxDynamicSharedMemorySize, SMEM_BYTES);
    msa_pass1<<<B_ROWS / ROWS, 64, SMEM_BYTES>>>(amp, pitch, bnd, decay, weights, out);
    msa_pass2<<<B_ROWS / P2_WARPS, P2_WARPS * 32>>>(out);
}

// round 5
// speedup vs baseline: 3.5056x; 1.2390x over previous
#include <cuda_runtime.h>
#include <cstdint>
#include <cstddef>

// Problem shape (fixed for this registry entry)
#define B_ROWS 4096
#define T_LEN  8192
#define K_WIN  5

// ---- pass-1 tiling ----
#define ROWS   32                 // rows per block (one lane per row in LIF/combiner warps)
#define WTILE  128                // timesteps per tile
#define NSTAGE 2                  // ring stages
#define NTILES (T_LEN / WTILE)    // 64
#define GPR    (WTILE / 4)        // 32 float4 per row-tile

// smem layout in float4 units; all tiles XOR-swizzled by (row&7) -> conflict-free, no pads
#define XS_BASE  0
#define SP_BASE  (NSTAGE * 3 * ROWS * GPR)          // 6144
#define SAL_BASE (2 * SP_BASE)                      // 12288
#define SMEM_F4  (SAL_BASE + NSTAGE * ROWS * GPR)   // 14336
#define SMEM_BYTES (SMEM_F4 * 16 + 8 * NSTAGE * 8)  // + 4 barrier kinds * NSTAGE

__device__ float g_max[B_ROWS];   // per-row raw-sal max (pass1 -> pass2)

// ---------------- mbarrier helpers ----------------
__device__ __forceinline__ void mbar_init(unsigned addr, unsigned count) {
    asm volatile("mbarrier.init.shared.b64 [%0], %1;" :: "r"(addr), "r"(count) : "memory");
}
__device__ __forceinline__ void mbar_arrive(unsigned addr) {
    asm volatile("mbarrier.arrive.shared.b64 _, [%0];" :: "r"(addr) : "memory");
}
__device__ __forceinline__ void mbar_wait(unsigned addr, unsigned parity) {
    unsigned done;
    asm volatile("{\n\t.reg .pred p;\n\t"
                 "mbarrier.try_wait.parity.acquire.cta.shared::cta.b64 p, [%1], %2;\n\t"
                 "selp.b32 %0, 1, 0, p;\n\t}"
                 : "=r"(done) : "r"(addr), "r"(parity) : "memory");
    if (!done) {
        asm volatile("{\n\t.reg .pred P1;\n\t"
                     "WL_%=:\n\t"
                     "mbarrier.try_wait.parity.acquire.cta.shared::cta.b64 P1, [%0], %1, 0x989680;\n\t"
                     "@P1 bra.uni WD_%=;\n\t"
                     "bra.uni WL_%=;\n\t"
                     "WD_%=:\n\t}"
                     :: "r"(addr), "r"(parity) : "memory");
    }
}
__device__ __forceinline__ void cp_async16(unsigned smem_addr, const void* gptr) {
    asm volatile("cp.async.cg.shared.global [%0], [%1], 16;" :: "r"(smem_addr), "l"(gptr));
}
__device__ __forceinline__ void cp_async_arrive_noinc(unsigned mbar_addr) {
    asm volatile("cp.async.mbarrier.arrive.noinc.shared.b64 [%0];" :: "r"(mbar_addr) : "memory");
}

// float mask: 1.0f if a >= 1.0f else 0.0f (FSET: fixed-lat, no predicate guard path)
__device__ __forceinline__ float fset_ge1(float a) {
    float m;
    asm("set.ge.f32.f32 %0, %1, %2;" : "=f"(m) : "f"(a), "f"(1.0f));
    return m;
}

// =====================================================================================
// Pass 1 — 6 warps:
//   warp 0   : producer  (cp.async x tiles in; coalesced STG of sal tiles out)
//   warps 1-3: LIF, one channel each, lane=row. 3-instr step: fmaf / set.ge / sub.
//   warp 4   : idle
//   warp 5   : combiner, lane=row: sal = w·masks, running row max, sal tile -> smem.
// Ring: x[2 stages], spikes[2 stages], sal[2 stages]. Barriers per stage:
//   full (32, cp.async)  cdone (96, LIF)  saldone (32, combiner)  salfree (32, producer)
// =====================================================================================
extern "C" __global__ void __launch_bounds__(192, 1)
msa_pass1(const float* __restrict__ amp, const float* __restrict__ pitch,
          const float* __restrict__ bnd, const float* __restrict__ decay,
          const float* __restrict__ weights, float* __restrict__ out)
{
    extern __shared__ float4 smem[];
    unsigned mbar_base = (unsigned)__cvta_generic_to_shared(smem + SMEM_F4);
    // byte offsets from mbar_base:
    //   full[s]    : s*8
    //   cdone[s]   : (NSTAGE + s)*8
    //   saldone[s] : (2*NSTAGE + s)*8
    //   salfree[s] : (3*NSTAGE + s)*8

    const int tid  = threadIdx.x;
    const int lane = tid & 31;
    const int warp = tid >> 5;
    const int b0   = blockIdx.x * ROWS;

    if (tid == 0) {
        #pragma unroll
        for (int s = 0; s < NSTAGE; ++s) {
            mbar_init(mbar_base + s * 8, 32);                   // full
            mbar_init(mbar_base + (NSTAGE + s) * 8, 96);        // cdone (3 LIF warps)
            mbar_init(mbar_base + (2 * NSTAGE + s) * 8, 32);    // saldone
            mbar_init(mbar_base + (3 * NSTAGE + s) * 8, 32);    // salfree
        }
        asm volatile("fence.proxy.async.shared::cta;" ::: "memory");
    }
    __syncthreads();

    float* out_sal = out + B_ROWS;

    if (warp == 4) return;   // idle warp (keeps producer & combiner on separate SMSPs)

    if (warp == 0) {
        // ---------------- producer: lane = 16B chunk (0..31) ----------------
        const int cc = lane;
        for (int i = 0; i < NTILES + NSTAGE; ++i) {
            const int s = i & 1;
            if (i >= NSTAGE) {
                const int j = i - NSTAGE;
                const unsigned par = (unsigned)((j >> 1) & 1);
                // drain sal tile j (combiner wrote it)
                mbar_wait(mbar_base + (2 * NSTAGE + s) * 8, par);
                const float4* SA = smem + SAL_BASE + s * ROWS * GPR;
                #pragma unroll 8
                for (int r = 0; r < ROWS; ++r) {
                    float4 vv = SA[r * GPR + (cc ^ (r & 7))];
                    *reinterpret_cast<float4*>(out_sal + (size_t)(b0 + r) * T_LEN
                                               + (size_t)j * WTILE + cc * 4) = vv;
                }
                mbar_arrive(mbar_base + (3 * NSTAGE + s) * 8);   // salfree
                // x slot s reusable once LIF warps finished tile j
                mbar_wait(mbar_base + (NSTAGE + s) * 8, par);
            }
            if (i < NTILES) {
                #pragma unroll
                for (int c = 0; c < 3; ++c) {
                    const float* src = (c == 0) ? amp : (c == 1) ? pitch : bnd;
                    float4* dst = smem + XS_BASE + (size_t)(s * 3 + c) * ROWS * GPR;
                    #pragma unroll 8
                    for (int r = 0; r < ROWS; ++r) {
                        unsigned sa = (unsigned)__cvta_generic_to_shared(
                            dst + r * GPR + (cc ^ (r & 7)));
                        cp_async16(sa, src + (size_t)(b0 + r) * T_LEN
                                       + (size_t)i * WTILE + cc * 4);
                    }
                }
                cp_async_arrive_noinc(mbar_base + s * 8);        // full
            }
        }
    } else if (warp <= 3) {
        // ---------------- LIF warp for channel c: lane = row ----------------
        const int c  = warp - 1;
        const int r  = lane;
        const int sw = r & 7;
        const float d = __ldg(&decay[c]);
        float v = 0.0f;

        for (int i = 0; i < NTILES; ++i) {
            const int s = i & 1;
            mbar_wait(mbar_base + s * 8, (unsigned)((i >> 1) & 1));            // x ready
            if (i >= NSTAGE)                                                    // spikes slot free
                mbar_wait(mbar_base + (2 * NSTAGE + s) * 8,
                          (unsigned)(((i - NSTAGE) >> 1) & 1));

            const float4* X  = smem + XS_BASE + ((size_t)(s * 3 + c) * ROWS + r) * GPR;
            float4*       SP = smem + SP_BASE + ((size_t)(s * 3 + c) * ROWS + r) * GPR;

            #pragma unroll
            for (int g = 0; g < GPR; ++g) {
                const int gs = g ^ sw;
                const float4 x = X[gs];
                float4 m;
                float a;
                a = fmaf(d, v, x.x); m.x = fset_ge1(a); v = a - m.x;
                a = fmaf(d, v, x.y); m.y = fset_ge1(a); v = a - m.y;
                a = fmaf(d, v, x.z); m.z = fset_ge1(a); v = a - m.z;
                a = fmaf(d, v, x.w); m.w = fset_ge1(a); v = a - m.w;
                SP[gs] = m;
            }
            mbar_arrive(mbar_base + (NSTAGE + s) * 8);   // cdone
        }
    } else {
        // ---------------- combiner (warp 5): lane = row ----------------
        const int r  = lane;
        const int sw = r & 7;
        const float w0 = __ldg(&weights[0]), w1 = __ldg(&weights[1]), w2 = __ldg(&weights[2]);
        float mx = 0.0f;

        for (int i = 0; i < NTILES; ++i) {
            const int s = i & 1;
            mbar_wait(mbar_base + (NSTAGE + s) * 8, (unsigned)((i >> 1) & 1));  // spikes ready
            if (i >= NSTAGE)                                                     // sal slot free
                mbar_wait(mbar_base + (3 * NSTAGE + s) * 8,
                          (unsigned)(((i - NSTAGE) >> 1) & 1));

            const float4* S0 = smem + SP_BASE + ((size_t)(s * 3 + 0) * ROWS + r) * GPR;
            const float4* S1 = smem + SP_BASE + ((size_t)(s * 3 + 1) * ROWS + r) * GPR;
            const float4* S2 = smem + SP_BASE + ((size_t)(s * 3 + 2) * ROWS + r) * GPR;
            float4*       SA = smem + SAL_BASE + ((size_t)s * ROWS + r) * GPR;

            #pragma unroll
            for (int g = 0; g < GPR; ++g) {
                const int gs = g ^ sw;
                const float4 m0 = S0[gs];
                const float4 m1 = S1[gs];
                const float4 m2 = S2[gs];
                float4 sv;
                sv.x = fmaf(w2, m2.x, fmaf(w1, m1.x, w0 * m0.x));
                sv.y = fmaf(w2, m2.y, fmaf(w1, m1.y, w0 * m0.y));
                sv.z = fmaf(w2, m2.z, fmaf(w1, m1.z, w0 * m0.z));
                sv.w = fmaf(w2, m2.w, fmaf(w1, m1.w, w0 * m0.w));
                SA[gs] = sv;
                mx = fmaxf(mx, fmaxf(fmaxf(sv.x, sv.y), fmaxf(sv.z, sv.w)));
            }
            mbar_arrive(mbar_base + (2 * NSTAGE + s) * 8);   // saldone
        }
        g_max[b0 + r] = mx;
    }
}

// ---------------- top-5 streaming insert (strict > preserves lowest-index ties) ----
__device__ __forceinline__ void top5_insert(float s, int t, float tv[5], int ti[5]) {
    if (s > tv[4]) {
        if (s > tv[0]) {
            tv[4]=tv[3]; ti[4]=ti[3]; tv[3]=tv[2]; ti[3]=ti[2];
            tv[2]=tv[1]; ti[2]=ti[1]; tv[1]=tv[0]; ti[1]=ti[0];
            tv[0]=s; ti[0]=t;
        } else if (s > tv[1]) {
            tv[4]=tv[3]; ti[4]=ti[3]; tv[3]=tv[2]; ti[3]=ti[2];
            tv[2]=tv[1]; ti[2]=ti[1]; tv[1]=s; ti[1]=t;
        } else if (s > tv[2]) {
            tv[4]=tv[3]; ti[4]=ti[3]; tv[3]=tv[2]; ti[3]=ti[2];
            tv[2]=s; ti[2]=t;
        } else if (s > tv[3]) {
            tv[4]=tv[3]; ti[4]=ti[3]; tv[3]=s; ti[3]=t;
        } else {
            tv[4]=s; ti[4]=t;
        }
    }
}

// =====================================================================================
// Pass 2: 2 warps per row (half-row each). Per iter: 4 batched LDG.128 (MLP=4),
// scale, vector pre-max gate before the top-5 ladder (almost always skipped),
// 4 STG.128. Then warp-level 64-bit-key merge + cross-warp sorted 5+5 merge.
// =====================================================================================
extern "C" __global__ void __launch_bounds__(256)
msa_pass2(float* __restrict__ out)
{
    __shared__ float s_tv[8][K_WIN];
    __shared__ int   s_ti[8][K_WIN];

    const int warp = threadIdx.x >> 5;
    const int lane = threadIdx.x & 31;
    const int rp   = warp >> 1;          // row within block (0..3)
    const int half = warp & 1;           // which half of the row
    const int row  = blockIdx.x * 4 + rp;

    const float inv = 1.0f / (g_max[row] + 1e-6f);
    float4* sal4 = reinterpret_cast<float4*>(out + B_ROWS)
                 + (size_t)row * (T_LEN / 4) + (size_t)half * (T_LEN / 8);
    const int tb = half * (T_LEN / 2);

    float tv[K_WIN] = {-1.0f, -1.0f, -1.0f, -1.0f, -1.0f};
    int   ti[K_WIN] = {0, 0, 0, 0, 0};

    for (int it = 0; it < 8; ++it) {     // 8 iters x 4 f4 x 32 lanes = 1024 f4 = half row
        float4 v[4];
        #pragma unroll
        for (int k = 0; k < 4; ++k) v[k] = sal4[it * 128 + k * 32 + lane];
        #pragma unroll
        for (int k = 0; k < 4; ++k) {
            v[k].x *= inv; v[k].y *= inv; v[k].z *= inv; v[k].w *= inv;
        }
        #pragma unroll
        for (int k = 0; k < 4; ++k) sal4[it * 128 + k * 32 + lane] = v[k];

        float pm = fmaxf(fmaxf(fmaxf(v[0].x, v[0].y), fmaxf(v[0].z, v[0].w)),
                   fmaxf(fmaxf(fmaxf(v[1].x, v[1].y), fmaxf(v[1].z, v[1].w)),
                   fmaxf(fmaxf(fmaxf(v[2].x, v[2].y), fmaxf(v[2].z, v[2].w)),
                         fmaxf(fmaxf(v[3].x, v[3].y), fmaxf(v[3].z, v[3].w)))));
        if (pm > tv[4]) {                // rare after warm-up: sal is near-quantized
            #pragma unroll
            for (int k = 0; k < 4; ++k) {
                const int t = tb + (it * 128 + k * 32 + lane) * 4;
                top5_insert(v[k].x, t + 0, tv, ti);
                top5_insert(v[k].y, t + 1, tv, ti);
                top5_insert(v[k].z, t + 2, tv, ti);
                top5_insert(v[k].w, t + 3, tv, ti);
            }
        }
    }

    // ---- warp merge: 5 rounds of 64-bit argmax (valbits<<32 | ~idx) ----
    float rv[K_WIN]; int ri[K_WIN];
    #pragma unroll
    for (int k = 0; k < K_WIN; ++k) {
        unsigned long long key = (tv[0] >= 0.0f)
            ? ((((unsigned long long)__float_as_uint(tv[0])) << 32) | (unsigned)(~(unsigned)ti[0]))
            : 0ULL;
        unsigned long long red = key;
        #pragma unroll
        for (int off = 16; off > 0; off >>= 1) {
            unsigned long long o = __shfl_xor_sync(0xffffffffu, red, off);
            red = (o > red) ? o : red;
        }
        if (key == red && red != 0ULL) {   // this lane's head won: pop
            tv[0]=tv[1]; ti[0]=ti[1];
            tv[1]=tv[2]; ti[1]=ti[2];
            tv[2]=tv[3]; ti[2]=ti[3];
            tv[3]=tv[4]; ti[3]=ti[4];
            tv[4]=-1.0f;
        }
        rv[k] = __uint_as_float((unsigned)(red >> 32));
        ri[k] = (int)(~(unsigned)(red & 0xFFFFFFFFu));
    }

    if (lane == 0) {
        #pragma unroll
        for (int k = 0; k < K_WIN; ++k) { s_tv[warp][k] = rv[k]; s_ti[warp][k] = ri[k]; }
    }
    __syncthreads();

    // ---- cross-warp merge of two sorted 5-lists (half 0 wins ties: lower indices) ----
    if (half == 0 && lane == 0) {
        float mv[K_WIN]; int mi[K_WIN];
        int ia = 0, ib = 0;
        #pragma unroll
        for (int k = 0; k < K_WIN; ++k) {
            const float av = s_tv[warp][ia];
            const float bv = s_tv[warp + 1][ib];
            if (av >= bv) { mv[k] = av; mi[k] = s_ti[warp][ia]; ++ia; }
            else          { mv[k] = bv; mi[k] = s_ti[warp + 1][ib]; ++ib; }
        }
        const float avg = (mv[0] + mv[1] + mv[2] + mv[3] + mv[4]) * 0.2f;
        out[row] = 0.5f + 2.0f * tanhf(1.8f * avg);
        float* out_idx = out + B_ROWS + (size_t)B_ROWS * T_LEN;
        #pragma unroll
        for (int k = 0; k < K_WIN; ++k)
            out_idx[(size_t)row * K_WIN + k] = (float)mi[k];
    }
}

extern "C" void kernel_launch(void* const* d_in, const int* in_sizes, int n_in,
                              void* d_out, int out_size) {
    (void)in_sizes; (void)n_in; (void)out_size;
    const float* amp     = (const float*)d_in[0];
    const float* pitch   = (const float*)d_in[1];
    const float* bnd     = (const float*)d_in[2];
    const float* decay   = (const float*)d_in[3];
    const float* weights = (const float*)d_in[4];
    float* out = (float*)d_out;

    cudaFuncSetAttribute(msa_pass1, cudaFuncAttributeMaxDynamicSharedMemorySize, SMEM_BYTES);
    msa_pass1<<<B_ROWS / ROWS, 192, SMEM_BYTES>>>(amp, pitch, bnd, decay, weights, out);
    msa_pass2<<<B_ROWS / 4, 256>>>(out);
}

// round 6
// speedup vs baseline: 4.8963x; 1.3967x over previous
#include <cuda_runtime.h>
#include <cstdint>
#include <cstddef>

// Problem shape (fixed for this registry entry)
#define B_ROWS 4096
#define T_LEN  8192
#define K_WIN  5

// ---- pass-1 tiling ----
#define ROWS   32                 // rows per block (one lane per row in LIF/combiner warps)
#define WTILE  128                // timesteps per tile
#define NSTAGE 2                  // ring stages
#define NTILES (T_LEN / WTILE)    // 64
#define GPR    (WTILE / 4)        // 32 float4 per row-tile

// smem layout in float4 units; tiles XOR-swizzled by (row&7) -> conflict-free, no pads
#define XS_BASE  0
#define SP_BASE  (NSTAGE * 3 * ROWS * GPR)          // 6144
#define SAL_BASE (2 * SP_BASE)                      // 12288
#define SMEM_F4  (SAL_BASE + NSTAGE * ROWS * GPR)   // 14336
#define SMEM_BYTES (SMEM_F4 * 16 + 8 * NSTAGE * 8)

__device__ float g_inv[B_ROWS];   // per-row 1/(max+eps) (pass1 -> pass2)

#define PAR(i) ((unsigned)((((unsigned)(i)) >> 1) & 1u))

// ---------------- mbarrier helpers ----------------
__device__ __forceinline__ void mbar_init(unsigned addr, unsigned count) {
    asm volatile("mbarrier.init.shared.b64 [%0], %1;" :: "r"(addr), "r"(count) : "memory");
}
__device__ __forceinline__ void mbar_arrive(unsigned addr) {
    asm volatile("mbarrier.arrive.shared.b64 _, [%0];" :: "r"(addr) : "memory");
}
__device__ __forceinline__ void mbar_wait(unsigned addr, unsigned parity) {
    unsigned done;
    asm volatile("{\n\t.reg .pred p;\n\t"
                 "mbarrier.try_wait.parity.acquire.cta.shared::cta.b64 p, [%1], %2;\n\t"
                 "selp.b32 %0, 1, 0, p;\n\t}"
                 : "=r"(done) : "r"(addr), "r"(parity) : "memory");
    if (!done) {
        asm volatile("{\n\t.reg .pred P1;\n\t"
                     "WL_%=:\n\t"
                     "mbarrier.try_wait.parity.acquire.cta.shared::cta.b64 P1, [%0], %1, 0x989680;\n\t"
                     "@P1 bra.uni WD_%=;\n\t"
                     "bra.uni WL_%=;\n\t"
                     "WD_%=:\n\t}"
                     :: "r"(addr), "r"(parity) : "memory");
    }
}
__device__ __forceinline__ void cp_async16(unsigned smem_addr, const void* gptr) {
    asm volatile("cp.async.cg.shared.global [%0], [%1], 16;" :: "r"(smem_addr), "l"(gptr));
}
__device__ __forceinline__ void cp_async_arrive_noinc(unsigned mbar_addr) {
    asm volatile("cp.async.mbarrier.arrive.noinc.shared.b64 [%0];" :: "r"(mbar_addr) : "memory");
}

// ---------------- top-5 streaming insert (strict > preserves lowest-index ties) ----
__device__ __forceinline__ void top5_insert(float s, int t, float tv[5], int ti[5]) {
    if (s > tv[4]) {
        if (s > tv[0]) {
            tv[4]=tv[3]; ti[4]=ti[3]; tv[3]=tv[2]; ti[3]=ti[2];
            tv[2]=tv[1]; ti[2]=ti[1]; tv[1]=tv[0]; ti[1]=ti[0];
            tv[0]=s; ti[0]=t;
        } else if (s > tv[1]) {
            tv[4]=tv[3]; ti[4]=ti[3]; tv[3]=tv[2]; ti[3]=ti[2];
            tv[2]=tv[1]; ti[2]=ti[1]; tv[1]=s; ti[1]=t;
        } else if (s > tv[2]) {
            tv[4]=tv[3]; ti[4]=ti[3]; tv[3]=tv[2]; ti[3]=ti[2];
            tv[2]=s; ti[2]=t;
        } else if (s > tv[3]) {
            tv[4]=tv[3]; ti[4]=ti[3]; tv[3]=s; ti[3]=t;
        } else {
            tv[4]=s; ti[4]=t;
        }
    }
}

// Exact LIF step: FSETP (pred) + FSEL, u=a-1 off-chain (Sterbenz-exact).
// Chain: FMA -> FSETP -> FSEL ~= 13 cyc.
__device__ __forceinline__ float lif1(float x, float d, float& v) {
    float a = fmaf(d, v, x);
    float u = a - 1.0f;
    bool  p = (a >= 1.0f);
    v = p ? u : a;
    return p ? 1.0f : 0.0f;
}

// =====================================================================================
// Pass 1 — 8 warps (warps 4 & 7 exit):
//   warp 0 (SMSP0): filler   — cp.async x tiles into the 2-stage ring
//   warps 1-3      : LIF, one channel each, lane=row, prefetched groups
//   warp 5 (SMSP1) : combiner — sal = w·masks, row max, gated top-5, mu/idx/g_inv
//   warp 6 (SMSP2) : drainer  — coalesced STG of raw sal tiles
// Barriers per slot s: full(32,cp.async) cdone(96,LIF) saldone(32,comb) salfree(32,drain)
// =====================================================================================
extern "C" __global__ void __launch_bounds__(256, 1)
msa_pass1(const float* __restrict__ amp, const float* __restrict__ pitch,
          const float* __restrict__ bnd, const float* __restrict__ decay,
          const float* __restrict__ weights, float* __restrict__ out)
{
    extern __shared__ float4 smem[];
    unsigned mbar_base = (unsigned)__cvta_generic_to_shared(smem + SMEM_F4);
    // full[s]: s*8 ; cdone[s]: (2+s)*8 ; saldone[s]: (4+s)*8 ; salfree[s]: (6+s)*8

    const int tid  = threadIdx.x;
    const int lane = tid & 31;
    const int warp = tid >> 5;
    const int b0   = blockIdx.x * ROWS;

    if (tid == 0) {
        #pragma unroll
        for (int s = 0; s < NSTAGE; ++s) {
            mbar_init(mbar_base + (0 + s) * 8, 32);   // full
            mbar_init(mbar_base + (2 + s) * 8, 96);   // cdone
            mbar_init(mbar_base + (4 + s) * 8, 32);   // saldone
            mbar_init(mbar_base + (6 + s) * 8, 32);   // salfree
        }
        asm volatile("fence.proxy.async.shared::cta;" ::: "memory");
    }
    __syncthreads();

    if (warp == 4 || warp == 7) return;

    float* out_sal = out + B_ROWS;

    if (warp == 0) {
        // ---------------- filler: lane = 16B chunk (0..31) ----------------
        const int cc = lane;
        for (int i = 0; i < NTILES; ++i) {
            const int s = i & 1;
            if (i >= NSTAGE)
                mbar_wait(mbar_base + (2 + s) * 8, PAR(i - 2));   // LIF done with slot
            #pragma unroll
            for (int c = 0; c < 3; ++c) {
                const float* src = (c == 0) ? amp : (c == 1) ? pitch : bnd;
                float4* dst = smem + XS_BASE + (size_t)(s * 3 + c) * ROWS * GPR;
                #pragma unroll 8
                for (int r = 0; r < ROWS; ++r) {
                    unsigned sa = (unsigned)__cvta_generic_to_shared(
                        dst + r * GPR + (cc ^ (r & 7)));
                    cp_async16(sa, src + (size_t)(b0 + r) * T_LEN
                                   + (size_t)i * WTILE + cc * 4);
                }
            }
            cp_async_arrive_noinc(mbar_base + (0 + s) * 8);       // full
        }
    } else if (warp <= 3) {
        // ---------------- LIF warp for channel c: lane = row ----------------
        const int c  = warp - 1;
        const int r  = lane;
        const int sw = r & 7;
        const float d = __ldg(&decay[c]);
        float v = 0.0f;

        for (int i = 0; i < NTILES; ++i) {
            const int s = i & 1;
            mbar_wait(mbar_base + (0 + s) * 8, PAR(i));           // x ready
            if (i >= NSTAGE)
                mbar_wait(mbar_base + (4 + s) * 8, PAR(i - 2));   // SP slot free

            const float4* X  = smem + XS_BASE + ((size_t)(s * 3 + c) * ROWS + r) * GPR;
            float4*       SP = smem + SP_BASE + ((size_t)(s * 3 + c) * ROWS + r) * GPR;

            float4 nxt = X[0 ^ sw];
            #pragma unroll 8
            for (int g = 0; g < GPR; ++g) {
                const float4 x = nxt;
                if (g + 1 < GPR) nxt = X[(g + 1) ^ sw];   // prefetch hides LDS latency
                float4 m;
                m.x = lif1(x.x, d, v);
                m.y = lif1(x.y, d, v);
                m.z = lif1(x.z, d, v);
                m.w = lif1(x.w, d, v);
                SP[g ^ sw] = m;
            }
            mbar_arrive(mbar_base + (2 + s) * 8);                 // cdone
        }
    } else if (warp == 5) {
        // ---------------- combiner: lane = row ----------------
        const int r  = lane;
        const int sw = r & 7;
        const float w0 = __ldg(&weights[0]), w1 = __ldg(&weights[1]), w2 = __ldg(&weights[2]);
        float mx = 0.0f;
        float tv[K_WIN] = {-1.0f, -1.0f, -1.0f, -1.0f, -1.0f};
        int   ti[K_WIN] = {0, 0, 0, 0, 0};

        for (int i = 0; i < NTILES; ++i) {
            const int s = i & 1;
            mbar_wait(mbar_base + (2 + s) * 8, PAR(i));           // spikes ready
            if (i >= NSTAGE)
                mbar_wait(mbar_base + (6 + s) * 8, PAR(i - 2));   // sal slot free

            const float4* S0 = smem + SP_BASE + ((size_t)(s * 3 + 0) * ROWS + r) * GPR;
            const float4* S1 = smem + SP_BASE + ((size_t)(s * 3 + 1) * ROWS + r) * GPR;
            const float4* S2 = smem + SP_BASE + ((size_t)(s * 3 + 2) * ROWS + r) * GPR;
            float4*       SA = smem + SAL_BASE + ((size_t)s * ROWS + r) * GPR;

            float tm = -1.0f;   // tile max
            #pragma unroll 8
            for (int g = 0; g < GPR; ++g) {
                const int gs = g ^ sw;
                const float4 m0 = S0[gs];
                const float4 m1 = S1[gs];
                const float4 m2 = S2[gs];
                float4 sv;
                sv.x = fmaf(w2, m2.x, fmaf(w1, m1.x, w0 * m0.x));
                sv.y = fmaf(w2, m2.y, fmaf(w1, m1.y, w0 * m0.y));
                sv.z = fmaf(w2, m2.z, fmaf(w1, m1.z, w0 * m0.z));
                sv.w = fmaf(w2, m2.w, fmaf(w1, m1.w, w0 * m0.w));
                SA[gs] = sv;
                tm = fmaxf(tm, fmaxf(fmaxf(sv.x, sv.y), fmaxf(sv.z, sv.w)));
            }
            mx = fmaxf(mx, tm);

            // Gated top-5 rescan: only when this tile beats the current 5th value.
            // After tv[4] saturates at the row max (quantized sal), never taken.
            if (tm > tv[4]) {
                const int tb = i * WTILE;
                for (int g = 0; g < GPR; ++g) {
                    const float4 sv = SA[g ^ sw];
                    const int t = tb + g * 4;
                    top5_insert(sv.x, t + 0, tv, ti);
                    top5_insert(sv.y, t + 1, tv, ti);
                    top5_insert(sv.z, t + 2, tv, ti);
                    top5_insert(sv.w, t + 3, tv, ti);
                }
            }
            mbar_arrive(mbar_base + (4 + s) * 8);                 // saldone
        }

        // ---- row tail: g_inv, mu, topk_idx ----
        const int b = b0 + r;
        const float inv = 1.0f / (mx + 1e-6f);
        g_inv[b] = inv;
        const float n0 = tv[0]*inv, n1 = tv[1]*inv, n2 = tv[2]*inv,
                    n3 = tv[3]*inv, n4 = tv[4]*inv;
        const float avg = ((((n0 + n1) + n2) + n3) + n4) / 5.0f;
        out[b] = 0.5f + 2.0f * tanhf(1.8f * avg);
        float* out_idx = out + B_ROWS + (size_t)B_ROWS * T_LEN;
        #pragma unroll
        for (int k = 0; k < K_WIN; ++k)
            out_idx[(size_t)b * K_WIN + k] = (float)ti[k];
    } else {
        // ---------------- drainer (warp 6): lane = 16B chunk ----------------
        const int cc = lane;
        for (int j = 0; j < NTILES; ++j) {
            const int s = j & 1;
            mbar_wait(mbar_base + (4 + s) * 8, PAR(j));           // sal ready
            const float4* SA = smem + SAL_BASE + (size_t)s * ROWS * GPR;
            #pragma unroll 8
            for (int r = 0; r < ROWS; ++r) {
                float4 vv = SA[r * GPR + (cc ^ (r & 7))];
                *reinterpret_cast<float4*>(out_sal + (size_t)(b0 + r) * T_LEN
                                           + (size_t)j * WTILE + cc * 4) = vv;
            }
            mbar_arrive(mbar_base + (6 + s) * 8);                 // salfree
        }
    }
}

// =====================================================================================
// Pass 2: pure in-place row scale (sal *= g_inv[row]) — streaming, DRAM-bound.
// =====================================================================================
extern "C" __global__ void __launch_bounds__(256)
msa_pass2(float4* __restrict__ sal4)
{
    const int i = blockIdx.x * blockDim.x + threadIdx.x;   // one float4 per thread
    const int row = i >> 11;                               // 2048 float4 per row
    const float inv = __ldg(&g_inv[row]);
    float4 v = sal4[i];
    v.x *= inv; v.y *= inv; v.z *= inv; v.w *= inv;
    sal4[i] = v;
}

extern "C" void kernel_launch(void* const* d_in, const int* in_sizes, int n_in,
                              void* d_out, int out_size) {
    (void)in_sizes; (void)n_in; (void)out_size;
    const float* amp     = (const float*)d_in[0];
    const float* pitch   = (const float*)d_in[1];
    const float* bnd     = (const float*)d_in[2];
    const float* decay   = (const float*)d_in[3];
    const float* weights = (const float*)d_in[4];
    float* out = (float*)d_out;

    cudaFuncSetAttribute(msa_pass1, cudaFuncAttributeMaxDynamicSharedMemorySize, SMEM_BYTES);
    msa_pass1<<<B_ROWS / ROWS, 256, SMEM_BYTES>>>(amp, pitch, bnd, decay, weights, out);

    const int n4 = B_ROWS * (T_LEN / 4);
    msa_pass2<<<n4 / 256, 256>>>(reinterpret_cast<float4*>(out + B_ROWS));
}

// round 7
// speedup vs baseline: 4.9627x; 1.0136x over previous
#include <cuda_runtime.h>
#include <cstdint>
#include <cstddef>

// Problem shape (fixed for this registry entry)
#define B_ROWS 4096
#define T_LEN  8192
#define K_WIN  5

// ---- pass-1 tiling ----
#define ROWS   32                 // rows per block (one lane per row in LIF/combiner warps)
#define WTILE  128                // timesteps per tile
#define NSTAGE 2                  // ring stages
#define NTILES (T_LEN / WTILE)    // 64
#define GPR    (WTILE / 4)        // 32 float4 per row-tile
#define RSTR   33                 // padded row stride (f4): bank=(r+g)%32 -> conflict-free

#define X_F4   (NSTAGE * 3 * ROWS * RSTR)   // 6336 f4 = 101.4 KB
#define SP_F4  (NSTAGE * 3 * ROWS * RSTR)   // 6336 f4 = 101.4 KB
#define SMEM_F4 (X_F4 + SP_F4)
#define SMEM_BYTES (SMEM_F4 * 16)           // 202,752 B

__device__ float g_inv[B_ROWS];   // per-row 1/(max+eps) (pass1 -> pass2)

#define PAR(i) ((unsigned)((((unsigned)(i)) >> 1) & 1u))

// ---------------- mbarrier helpers ----------------
__device__ __forceinline__ void mbar_init(unsigned addr, unsigned count) {
    asm volatile("mbarrier.init.shared.b64 [%0], %1;" :: "r"(addr), "r"(count) : "memory");
}
__device__ __forceinline__ void mbar_arrive(unsigned addr) {
    asm volatile("mbarrier.arrive.shared.b64 _, [%0];" :: "r"(addr) : "memory");
}
__device__ __forceinline__ void mbar_wait(unsigned addr, unsigned parity) {
    unsigned done;
    asm volatile("{\n\t.reg .pred p;\n\t"
                 "mbarrier.try_wait.parity.acquire.cta.shared::cta.b64 p, [%1], %2;\n\t"
                 "selp.b32 %0, 1, 0, p;\n\t}"
                 : "=r"(done) : "r"(addr), "r"(parity) : "memory");
    if (!done) {
        asm volatile("{\n\t.reg .pred P1;\n\t"
                     "WL_%=:\n\t"
                     "mbarrier.try_wait.parity.acquire.cta.shared::cta.b64 P1, [%0], %1, 0x989680;\n\t"
                     "@P1 bra.uni WD_%=;\n\t"
                     "bra.uni WL_%=;\n\t"
                     "WD_%=:\n\t}"
                     :: "r"(addr), "r"(parity) : "memory");
    }
}
__device__ __forceinline__ void cp_async16(unsigned smem_addr, const void* gptr) {
    asm volatile("cp.async.cg.shared.global [%0], [%1], 16;" :: "r"(smem_addr), "l"(gptr));
}
__device__ __forceinline__ void cp_async_arrive_noinc(unsigned mbar_addr) {
    asm volatile("cp.async.mbarrier.arrive.noinc.shared.b64 [%0];" :: "r"(mbar_addr) : "memory");
}

// ---------------- top-5 streaming insert (strict > preserves lowest-index ties) ----
__device__ __forceinline__ void top5_insert(float s, int t, float tv[5], int ti[5]) {
    if (s > tv[4]) {
        if (s > tv[0]) {
            tv[4]=tv[3]; ti[4]=ti[3]; tv[3]=tv[2]; ti[3]=ti[2];
            tv[2]=tv[1]; ti[2]=ti[1]; tv[1]=tv[0]; ti[1]=ti[0];
            tv[0]=s; ti[0]=t;
        } else if (s > tv[1]) {
            tv[4]=tv[3]; ti[4]=ti[3]; tv[3]=tv[2]; ti[3]=ti[2];
            tv[2]=tv[1]; ti[2]=ti[1]; tv[1]=s; ti[1]=t;
        } else if (s > tv[2]) {
            tv[4]=tv[3]; ti[4]=ti[3]; tv[3]=tv[2]; ti[3]=ti[2];
            tv[2]=s; ti[2]=t;
        } else if (s > tv[3]) {
            tv[4]=tv[3]; ti[4]=ti[3]; tv[3]=s; ti[3]=t;
        } else {
            tv[4]=s; ti[4]=t;
        }
    }
}

// Exact LIF step: FSETP (pred-as-data) + FSEL, u=a-1 off-chain (Sterbenz-exact).
__device__ __forceinline__ float lif1(float x, float d, float& v) {
    float a = fmaf(d, v, x);
    float u = a - 1.0f;
    bool  p = (a >= 1.0f);
    v = p ? u : a;
    return p ? 1.0f : 0.0f;
}

// =====================================================================================
// Pass 1 — 8 warps (warp 7 exits):
//   warps 0,4 (SMSP0): fillers — cp.async x tiles (rows 0-15 / 16-31), 2x in-flight
//   warps 1-3        : LIF, one channel each, lane=row, prefetched, conflict-free LDS/STS
//   warp 5 (SMSP1)   : combiner — sal from spike masks, row max, gated top-5, mu/idx/g_inv
//   warp 6 (SMSP2)   : drainer  — recomputes sal from spike masks, coalesced STG
// Barriers per slot s: full(64,cp.async) cdone(96,LIF) sdone(64,comb+drain)
// =====================================================================================
extern "C" __global__ void __launch_bounds__(256, 1)
msa_pass1(const float* __restrict__ amp, const float* __restrict__ pitch,
          const float* __restrict__ bnd, const float* __restrict__ decay,
          const float* __restrict__ weights, float* __restrict__ out)
{
    extern __shared__ float4 smem[];
    float4* smx = smem;            // x tiles
    float4* smp = smem + X_F4;     // spike-mask tiles
    __shared__ __align__(8) unsigned long long s_mb[6];
    unsigned mbar_base = (unsigned)__cvta_generic_to_shared(s_mb);
    // full[s]: s*8 ; cdone[s]: (2+s)*8 ; sdone[s]: (4+s)*8

    const int tid  = threadIdx.x;
    const int lane = tid & 31;
    const int warp = tid >> 5;
    const int b0   = blockIdx.x * ROWS;

    if (tid == 0) {
        #pragma unroll
        for (int s = 0; s < NSTAGE; ++s) {
            mbar_init(mbar_base + (0 + s) * 8, 64);   // full (2 filler warps x 32)
            mbar_init(mbar_base + (2 + s) * 8, 96);   // cdone (3 LIF warps)
            mbar_init(mbar_base + (4 + s) * 8, 64);   // sdone (combiner + drainer)
        }
        asm volatile("fence.proxy.async.shared::cta;" ::: "memory");
    }
    __syncthreads();

    if (warp == 7) return;

    float* out_sal = out + B_ROWS;

    if (warp == 0 || warp == 4) {
        // ---------------- fillers: lane = 16B chunk (0..31), each covers 16 rows ----
        const int cc = lane;
        const int rbase = (warp == 0) ? 0 : 16;
        for (int i = 0; i < NTILES; ++i) {
            const int s = i & 1;
            if (i >= NSTAGE)
                mbar_wait(mbar_base + (2 + s) * 8, PAR(i - 2));   // LIF done with X slot
            #pragma unroll
            for (int c = 0; c < 3; ++c) {
                const float* src = (c == 0) ? amp : (c == 1) ? pitch : bnd;
                float4* dst = smx + (size_t)(s * 3 + c) * ROWS * RSTR;
                #pragma unroll 8
                for (int q = 0; q < 16; ++q) {
                    const int r = rbase + q;
                    unsigned sa = (unsigned)__cvta_generic_to_shared(dst + r * RSTR + cc);
                    cp_async16(sa, src + (size_t)(b0 + r) * T_LEN
                                   + (size_t)i * WTILE + cc * 4);
                }
            }
            cp_async_arrive_noinc(mbar_base + (0 + s) * 8);       // full
        }
    } else if (warp <= 3) {
        // ---------------- LIF warp for channel c: lane = row ----------------
        const int c = warp - 1;
        const int r = lane;
        const float d = __ldg(&decay[c]);
        float v = 0.0f;

        for (int i = 0; i < NTILES; ++i) {
            const int s = i & 1;
            mbar_wait(mbar_base + (0 + s) * 8, PAR(i));           // x ready
            if (i >= NSTAGE)
                mbar_wait(mbar_base + (4 + s) * 8, PAR(i - 2));   // SP slot free

            const float4* X  = smx + ((size_t)(s * 3 + c) * ROWS + r) * RSTR;
            float4*       SP = smp + ((size_t)(s * 3 + c) * ROWS + r) * RSTR;

            float4 nxt = X[0];
            #pragma unroll 8
            for (int g = 0; g < GPR; ++g) {
                const float4 x = nxt;
                if (g + 1 < GPR) nxt = X[g + 1];   // prefetch hides LDS latency
                float4 m;
                m.x = lif1(x.x, d, v);
                m.y = lif1(x.y, d, v);
                m.z = lif1(x.z, d, v);
                m.w = lif1(x.w, d, v);
                SP[g] = m;
            }
            mbar_arrive(mbar_base + (2 + s) * 8);                 // cdone
        }
    } else if (warp == 5) {
        // ---------------- combiner: lane = row; no stores, only max/top-5 ----------
        const int r = lane;
        const float w0 = __ldg(&weights[0]), w1 = __ldg(&weights[1]), w2 = __ldg(&weights[2]);
        float mx = 0.0f;
        float tv[K_WIN] = {-1.0f, -1.0f, -1.0f, -1.0f, -1.0f};
        int   ti[K_WIN] = {0, 0, 0, 0, 0};

        for (int i = 0; i < NTILES; ++i) {
            const int s = i & 1;
            mbar_wait(mbar_base + (2 + s) * 8, PAR(i));           // spikes ready

            const float4* S0 = smp + ((size_t)(s * 3 + 0) * ROWS + r) * RSTR;
            const float4* S1 = smp + ((size_t)(s * 3 + 1) * ROWS + r) * RSTR;
            const float4* S2 = smp + ((size_t)(s * 3 + 2) * ROWS + r) * RSTR;

            float tm = -1.0f;
            #pragma unroll 8
            for (int g = 0; g < GPR; ++g) {
                const float4 m0 = S0[g];
                const float4 m1 = S1[g];
                const float4 m2 = S2[g];
                float4 sv;
                sv.x = fmaf(w2, m2.x, fmaf(w1, m1.x, w0 * m0.x));
                sv.y = fmaf(w2, m2.y, fmaf(w1, m1.y, w0 * m0.y));
                sv.z = fmaf(w2, m2.z, fmaf(w1, m1.z, w0 * m0.z));
                sv.w = fmaf(w2, m2.w, fmaf(w1, m1.w, w0 * m0.w));
                tm = fmaxf(tm, fmaxf(fmaxf(sv.x, sv.y), fmaxf(sv.z, sv.w)));
            }
            mx = fmaxf(mx, tm);

            // Gated rescan: only when this tile beats the current 5th value (rare).
            if (tm > tv[4]) {
                const int tb = i * WTILE;
                for (int g = 0; g < GPR; ++g) {
                    const float4 m0 = S0[g];
                    const float4 m1 = S1[g];
                    const float4 m2 = S2[g];
                    float4 sv;
                    sv.x = fmaf(w2, m2.x, fmaf(w1, m1.x, w0 * m0.x));
                    sv.y = fmaf(w2, m2.y, fmaf(w1, m1.y, w0 * m0.y));
                    sv.z = fmaf(w2, m2.z, fmaf(w1, m1.z, w0 * m0.z));
                    sv.w = fmaf(w2, m2.w, fmaf(w1, m1.w, w0 * m0.w));
                    const int t = tb + g * 4;
                    top5_insert(sv.x, t + 0, tv, ti);
                    top5_insert(sv.y, t + 1, tv, ti);
                    top5_insert(sv.z, t + 2, tv, ti);
                    top5_insert(sv.w, t + 3, tv, ti);
                }
            }
            mbar_arrive(mbar_base + (4 + s) * 8);                 // sdone (1 of 2)
        }

        // ---- row tail: g_inv, mu, topk_idx ----
        const int b = b0 + r;
        const float inv = 1.0f / (mx + 1e-6f);
        g_inv[b] = inv;
        const float n0 = tv[0]*inv, n1 = tv[1]*inv, n2 = tv[2]*inv,
                    n3 = tv[3]*inv, n4 = tv[4]*inv;
        const float avg = ((((n0 + n1) + n2) + n3) + n4) / 5.0f;
        out[b] = 0.5f + 2.0f * tanhf(1.8f * avg);
        float* out_idx = out + B_ROWS + (size_t)B_ROWS * T_LEN;
        #pragma unroll
        for (int k = 0; k < K_WIN; ++k)
            out_idx[(size_t)b * K_WIN + k] = (float)ti[k];
    } else {
        // ---------------- drainer (warp 6): lane = 16B chunk; recompute sal + STG ----
        const int cc = lane;
        const float w0 = __ldg(&weights[0]), w1 = __ldg(&weights[1]), w2 = __ldg(&weights[2]);
        for (int j = 0; j < NTILES; ++j) {
            const int s = j & 1;
            mbar_wait(mbar_base + (2 + s) * 8, PAR(j));           // spikes ready
            const float4* P0 = smp + (size_t)(s * 3 + 0) * ROWS * RSTR;
            const float4* P1 = smp + (size_t)(s * 3 + 1) * ROWS * RSTR;
            const float4* P2 = smp + (size_t)(s * 3 + 2) * ROWS * RSTR;
            #pragma unroll 4
            for (int r = 0; r < ROWS; ++r) {
                const float4 m0 = P0[r * RSTR + cc];
                const float4 m1 = P1[r * RSTR + cc];
                const float4 m2 = P2[r * RSTR + cc];
                float4 sv;
                sv.x = fmaf(w2, m2.x, fmaf(w1, m1.x, w0 * m0.x));
                sv.y = fmaf(w2, m2.y, fmaf(w1, m1.y, w0 * m0.y));
                sv.z = fmaf(w2, m2.z, fmaf(w1, m1.z, w0 * m0.z));
                sv.w = fmaf(w2, m2.w, fmaf(w1, m1.w, w0 * m0.w));
                *reinterpret_cast<float4*>(out_sal + (size_t)(b0 + r) * T_LEN
                                           + (size_t)j * WTILE + cc * 4) = sv;
            }
            mbar_arrive(mbar_base + (4 + s) * 8);                 // sdone (2 of 2)
        }
    }
}

// =====================================================================================
// Pass 2: pure in-place row scale (sal *= g_inv[row]) — streaming, DRAM-bound.
// =====================================================================================
extern "C" __global__ void __launch_bounds__(256)
msa_pass2(float4* __restrict__ sal4)
{
    const int i = blockIdx.x * blockDim.x + threadIdx.x;   // one float4 per thread
    const int row = i >> 11;                               // 2048 float4 per row
    const float inv = __ldg(&g_inv[row]);
    float4 v = sal4[i];
    v.x *= inv; v.y *= inv; v.z *= inv; v.w *= inv;
    sal4[i] = v;
}

extern "C" void kernel_launch(void* const* d_in, const int* in_sizes, int n_in,
                              void* d_out, int out_size) {
    (void)in_sizes; (void)n_in; (void)out_size;
    const float* amp     = (const float*)d_in[0];
    const float* pitch   = (const float*)d_in[1];
    const float* bnd     = (const float*)d_in[2];
    const float* decay   = (const float*)d_in[3];
    const float* weights = (const float*)d_in[4];
    float* out = (float*)d_out;

    cudaFuncSetAttribute(msa_pass1, cudaFuncAttributeMaxDynamicSharedMemorySize, SMEM_BYTES);
    msa_pass1<<<B_ROWS / ROWS, 256, SMEM_BYTES>>>(amp, pitch, bnd, decay, weights, out);

    const int n4 = B_ROWS * (T_LEN / 4);
    msa_pass2<<<n4 / 256, 256>>>(reinterpret_cast<float4*>(out + B_ROWS));
}